// round 1
// baseline (speedup 1.0000x reference)
#include <cuda_runtime.h>

#define DPC 90            // 10 + 80 classes
#define GRID_S 7

// accumulators: [0]=n_obj, [1]=coord_sum, [2]=conf_sum, [3]=class_sum
__device__ float g_acc[4];

__global__ void zero_acc_kernel() {
    if (threadIdx.x < 4) g_acc[threadIdx.x] = 0.0f;
}

__device__ __forceinline__ float iou_img(float cx1, float cy1, float w1, float h1,
                                         float cx2, float cy2, float w2, float h2) {
    float ix_min = fmaxf(cx1 - 0.5f * w1, cx2 - 0.5f * w2);
    float iy_min = fmaxf(cy1 - 0.5f * h1, cy2 - 0.5f * h2);
    float ix_max = fminf(cx1 + 0.5f * w1, cx2 + 0.5f * w2);
    float iy_max = fminf(cy1 + 0.5f * h1, cy2 + 0.5f * h2);
    float iw = fmaxf(ix_max - ix_min, 0.0f);
    float ih = fmaxf(iy_max - iy_min, 0.0f);
    float inter = iw * ih;
    float uni = w1 * h1 + w2 * h2 - inter;
    return inter / (uni + 1e-6f);
}

__global__ void __launch_bounds__(256)
yolo_loss_kernel(const float* __restrict__ pred,
                 const float* __restrict__ tgt,
                 int ncells) {
    const int lane   = threadIdx.x & 31;
    const int wid    = threadIdx.x >> 5;
    const int gwarp  = blockIdx.x * (blockDim.x >> 5) + wid;
    const int nwarps = gridDim.x * (blockDim.x >> 5);

    float a_n = 0.0f, a_co = 0.0f, a_cf = 0.0f, a_cl = 0.0f;

    for (int cell = gwarp; cell < ncells; cell += nwarps) {
        const float* p = pred + (size_t)cell * DPC;
        const float* t = tgt  + (size_t)cell * DPC;

        float p0 = __ldg(p + lane);
        float p1 = __ldg(p + lane + 32);
        float t0 = __ldg(t + lane);
        float t1 = __ldg(t + lane + 32);
        float p2 = 0.0f, t2 = 0.0f;
        if (lane < 26) {                 // indices 64..89
            p2 = __ldg(p + lane + 64);
            t2 = __ldg(t + lane + 64);
        }

        // class squared-error over indices [10, 90)
        float cs = 0.0f;
        if (lane >= 10) { float d = p0 - t0; cs = d * d; }          // idx 10..31
        { float d = p1 - t1; cs += d * d; }                         // idx 32..63
        { float d = p2 - t2; cs += d * d; }                         // idx 64..89 (0 for lane>=26)
        #pragma unroll
        for (int off = 16; off; off >>= 1)
            cs += __shfl_down_sync(0xffffffffu, cs, off);           // total in lane 0

        // broadcast box scalars from lanes 0..9 (pred) and 0..4 (target)
        const unsigned FULL = 0xffffffffu;
        float bx1 = __shfl_sync(FULL, p0, 0);
        float by1 = __shfl_sync(FULL, p0, 1);
        float bw1 = __shfl_sync(FULL, p0, 2);
        float bh1 = __shfl_sync(FULL, p0, 3);
        float bc1 = __shfl_sync(FULL, p0, 4);
        float bx2 = __shfl_sync(FULL, p0, 5);
        float by2 = __shfl_sync(FULL, p0, 6);
        float bw2 = __shfl_sync(FULL, p0, 7);
        float bh2 = __shfl_sync(FULL, p0, 8);
        float bc2 = __shfl_sync(FULL, p0, 9);
        float tx  = __shfl_sync(FULL, t0, 0);
        float ty  = __shfl_sync(FULL, t0, 1);
        float tw  = __shfl_sync(FULL, t0, 2);
        float th  = __shfl_sync(FULL, t0, 3);
        float tc  = __shfl_sync(FULL, t0, 4);

        if (lane == 0) {
            int gx = cell % GRID_S;
            int gy = (cell / GRID_S) % GRID_S;
            const float inv = 1.0f / (float)GRID_S;
            float fgx = (float)gx, fgy = (float)gy;

            float c1x = (fgx + bx1) * inv, c1y = (fgy + by1) * inv;
            float c2x = (fgx + bx2) * inv, c2y = (fgy + by2) * inv;
            float ctx = (fgx + tx)  * inv, cty = (fgy + ty)  * inv;

            float iou1 = iou_img(c1x, c1y, bw1, bh1, ctx, cty, tw, th);
            float iou2 = iou_img(c2x, c2y, bw2, bh2, ctx, cty, tw, th);
            bool r1 = iou1 > iou2;

            float bx = r1 ? bx1 : bx2;
            float by = r1 ? by1 : by2;
            float bw = r1 ? bw1 : bw2;
            float bh = r1 ? bh1 : bh2;
            float bc = r1 ? bc1 : bc2;

            float objf = (tc == 1.0f) ? 1.0f : 0.0f;

            float dx = bx - tx, dy = by - ty;
            float dxy2 = dx * dx + dy * dy;
            float sw = sqrtf(fmaxf(bw, 1e-6f)) - sqrtf(fmaxf(tw, 1e-6f));
            float sh = sqrtf(fmaxf(bh, 1e-6f)) - sqrtf(fmaxf(th, 1e-6f));
            float coord_per = 0.5f * (dxy2 + sw * sw + sh * sh);

            float co = bc - 1.0f;
            float conf = (objf != 0.0f) ? (co * co)
                                        : 0.5f * (bc1 * bc1 + bc2 * bc2);

            a_n  += objf;
            a_co += coord_per * objf;
            a_cf += conf;
            a_cl += cs * (1.0f / 80.0f) * objf;
        }
    }

    // block reduction: lane 0 of each warp -> shared, then 4 threads atomicAdd
    __shared__ float s_acc[8][4];
    if (lane == 0) {
        s_acc[wid][0] = a_n;
        s_acc[wid][1] = a_co;
        s_acc[wid][2] = a_cf;
        s_acc[wid][3] = a_cl;
    }
    __syncthreads();
    if (threadIdx.x < 4) {
        float s = 0.0f;
        const int nw = blockDim.x >> 5;
        #pragma unroll
        for (int w = 0; w < 8; ++w)
            if (w < nw) s += s_acc[w][threadIdx.x];
        atomicAdd(&g_acc[threadIdx.x], s);
    }
}

__global__ void finalize_kernel(float* __restrict__ out, float n_cells) {
    float n  = g_acc[0];
    float co = g_acc[1];
    float cf = g_acc[2];
    float cl = g_acc[3];
    float den = fmaxf(n, 1.0f);
    float conf_count = fmaxf(n + 2.0f * (n_cells - n), 1.0f);
    out[0] = 5.0f * (co / den) + cf / conf_count + cl / den;
}

extern "C" void kernel_launch(void* const* d_in, const int* in_sizes, int n_in,
                              void* d_out, int out_size) {
    const float* pred = (const float*)d_in[0];
    const float* tgt  = (const float*)d_in[1];
    float* out = (float*)d_out;

    int ncells = in_sizes[0] / DPC;   // B * S * S

    zero_acc_kernel<<<1, 32>>>();

    const int threads = 256;
    const int blocks  = 148 * 16;     // persistent-ish grid; ~2368 atomics/addr
    yolo_loss_kernel<<<blocks, threads>>>(pred, tgt, ncells);

    finalize_kernel<<<1, 1>>>(out, (float)ncells);
}

// round 2
// speedup vs baseline: 1.1702x; 1.1702x over previous
#include <cuda_runtime.h>

#define DPC 90            // 10 + 80 classes
#define GRID_S 7
#define TILE_STRIDE 18    // 15 staged floats per cell, padded; 72B rows (8B aligned)

// accumulators: [0]=n_obj, [1]=coord_sum, [2]=conf_sum, [3]=class_sum
__device__ float g_acc[4];
__device__ unsigned int g_done;

__device__ __forceinline__ float iou_img(float cx1, float cy1, float w1, float h1,
                                         float cx2, float cy2, float w2, float h2) {
    float ix_min = fmaxf(cx1 - 0.5f * w1, cx2 - 0.5f * w2);
    float iy_min = fmaxf(cy1 - 0.5f * h1, cy2 - 0.5f * h2);
    float ix_max = fminf(cx1 + 0.5f * w1, cx2 + 0.5f * w2);
    float iy_max = fminf(cy1 + 0.5f * h1, cy2 + 0.5f * h2);
    float iw = fmaxf(ix_max - ix_min, 0.0f);
    float ih = fmaxf(iy_max - iy_min, 0.0f);
    float inter = iw * ih;
    float uni = w1 * h1 + w2 * h2 - inter;
    return inter / (uni + 1e-6f);
}

__global__ void __launch_bounds__(256)
yolo_loss_kernel(const float* __restrict__ pred,
                 const float* __restrict__ tgt,
                 float* __restrict__ out,
                 int ncells) {
    const unsigned FULL = 0xffffffffu;
    const int lane   = threadIdx.x & 31;
    const int wid    = threadIdx.x >> 5;
    const int gwarp  = blockIdx.x * 8 + wid;
    const int nwarps = gridDim.x * 8;
    const int nchunks = (ncells + 31) >> 5;

    // per-warp smem tile: 32 cells x 18 floats (p[0..9] -> 0..9, t[0..4] -> 10..14)
    __shared__ float s_tile[8][32 * TILE_STRIDE];
    __shared__ float s_red[8][4];
    float* tile = s_tile[wid];

    float a_n = 0.0f, a_co = 0.0f, a_cf = 0.0f, a_cl = 0.0f;

    // hoisted lane predicates
    const bool ld_hi   = (lane < 26);   // elems 64..89
    const bool cls_lo  = (lane >= 10);  // elems 10..31 are class
    const bool stage_p = (lane < 10);
    const bool stage_t = (lane < 5);

    for (int chunk = gwarp; chunk < nchunks; chunk += nwarps) {
        const int base = chunk << 5;
        const int jmax = min(32, ncells - base);
        const float* pc = pred + (size_t)base * DPC;
        const float* tc_ = tgt + (size_t)base * DPC;

        // ---------- Phase A: coalesced stream, class MSE + staging ----------
        #pragma unroll 4
        for (int j = 0; j < jmax; ++j) {
            const float* p = pc  + j * DPC;
            const float* t = tc_ + j * DPC;
            float p0 = p[lane];
            float p1 = p[lane + 32];
            float t0 = t[lane];
            float t1 = t[lane + 32];
            float p2 = 0.0f, t2 = 0.0f;
            if (ld_hi) { p2 = p[lane + 64]; t2 = t[lane + 64]; }

            float tcv = __shfl_sync(FULL, t0, 4);
            float w = (tcv == 1.0f) ? 1.0f : 0.0f;

            float d0 = p0 - t0;
            float d1 = p1 - t1;
            float d2 = p2 - t2;
            float cs = d1 * d1;
            if (cls_lo) cs = fmaf(d0, d0, cs);
            cs = fmaf(d2, d2, cs);              // d2 == 0 for lane >= 26
            a_cl = fmaf(cs, w, a_cl);

            if (stage_p) tile[j * TILE_STRIDE + lane]      = p0;
            if (stage_t) tile[j * TILE_STRIDE + 10 + lane] = t0;
        }
        __syncwarp();

        // ---------- Phase B: lane-per-cell box math from smem ----------
        if (lane < jmax) {
            const float* T = tile + lane * TILE_STRIDE;
            float bx1 = T[0], by1 = T[1], bw1 = T[2], bh1 = T[3], bc1 = T[4];
            float bx2 = T[5], by2 = T[6], bw2 = T[7], bh2 = T[8], bc2 = T[9];
            float tx  = T[10], ty = T[11], tw = T[12], th = T[13], tcv = T[14];

            int cell = base + lane;
            int gx = cell % GRID_S;
            int gy = (cell / GRID_S) % GRID_S;
            const float inv = 1.0f / (float)GRID_S;
            float fgx = (float)gx, fgy = (float)gy;

            float c1x = (fgx + bx1) * inv, c1y = (fgy + by1) * inv;
            float c2x = (fgx + bx2) * inv, c2y = (fgy + by2) * inv;
            float ctx = (fgx + tx)  * inv, cty = (fgy + ty)  * inv;

            float iou1 = iou_img(c1x, c1y, bw1, bh1, ctx, cty, tw, th);
            float iou2 = iou_img(c2x, c2y, bw2, bh2, ctx, cty, tw, th);
            bool r1 = iou1 > iou2;

            float bx = r1 ? bx1 : bx2;
            float by = r1 ? by1 : by2;
            float bw = r1 ? bw1 : bw2;
            float bh = r1 ? bh1 : bh2;
            float bc = r1 ? bc1 : bc2;

            float objf = (tcv == 1.0f) ? 1.0f : 0.0f;

            float dx = bx - tx, dy = by - ty;
            float dxy2 = dx * dx + dy * dy;
            float sw = sqrtf(fmaxf(bw, 1e-6f)) - sqrtf(fmaxf(tw, 1e-6f));
            float sh = sqrtf(fmaxf(bh, 1e-6f)) - sqrtf(fmaxf(th, 1e-6f));
            float coord_per = 0.5f * (dxy2 + sw * sw + sh * sh);

            float co = bc - 1.0f;
            float conf = (objf != 0.0f) ? (co * co)
                                        : 0.5f * (bc1 * bc1 + bc2 * bc2);

            a_n  += objf;
            a_co += coord_per * objf;
            a_cf += conf;
        }
        __syncwarp();
    }

    // ---------- warp reduction ----------
    #pragma unroll
    for (int off = 16; off; off >>= 1) {
        a_n  += __shfl_down_sync(FULL, a_n,  off);
        a_co += __shfl_down_sync(FULL, a_co, off);
        a_cf += __shfl_down_sync(FULL, a_cf, off);
        a_cl += __shfl_down_sync(FULL, a_cl, off);
    }
    if (lane == 0) {
        s_red[wid][0] = a_n;
        s_red[wid][1] = a_co;
        s_red[wid][2] = a_cf;
        s_red[wid][3] = a_cl;
    }
    __syncthreads();

    // ---------- block -> global (REDG, no return value) ----------
    if (threadIdx.x < 4) {
        float s = 0.0f;
        #pragma unroll
        for (int w = 0; w < 8; ++w) s += s_red[w][threadIdx.x];
        atomicAdd(&g_acc[threadIdx.x], s);
    }
    __syncthreads();

    // ---------- last-block finalize (self-resetting) ----------
    if (threadIdx.x == 0) {
        __threadfence();
        unsigned int ticket = atomicAdd(&g_done, 1u);
        if (ticket == gridDim.x - 1) {
            __threadfence();
            volatile float* ga = g_acc;
            float n  = ga[0];
            float co = ga[1];
            float cf = ga[2];
            float cl = ga[3];
            float den = fmaxf(n, 1.0f);
            float conf_count = fmaxf(2.0f * (float)ncells - n, 1.0f);
            out[0] = 5.0f * (co / den) + cf / conf_count
                   + (cl * (1.0f / 80.0f)) / den;
            // reset for next (deterministic) replay
            ga[0] = 0.0f; ga[1] = 0.0f; ga[2] = 0.0f; ga[3] = 0.0f;
            __threadfence();
            g_done = 0u;
        }
    }
}

extern "C" void kernel_launch(void* const* d_in, const int* in_sizes, int n_in,
                              void* d_out, int out_size) {
    const float* pred = (const float*)d_in[0];
    const float* tgt  = (const float*)d_in[1];
    float* out = (float*)d_out;

    int ncells  = in_sizes[0] / DPC;       // B * S * S
    int nchunks = (ncells + 31) / 32;
    int blocks  = (nchunks + 7) / 8;       // 8 warps per block, 1 chunk per warp

    yolo_loss_kernel<<<blocks, 256>>>(pred, tgt, out, ncells);
}

// round 5
// speedup vs baseline: 1.6440x; 1.4049x over previous
#include <cuda_runtime.h>

#define DPC 90            // 10 + 80 classes
#define GRID_S 7

// accumulators: [0]=n_obj, [1]=coord_sum, [2]=conf_sum, [3]=class_sum
__device__ float g_acc[4];
__device__ unsigned int g_done;

__device__ __forceinline__ float iou_img(float cx1, float cy1, float w1, float h1,
                                         float cx2, float cy2, float w2, float h2) {
    float ix_min = fmaxf(cx1 - 0.5f * w1, cx2 - 0.5f * w2);
    float iy_min = fmaxf(cy1 - 0.5f * h1, cy2 - 0.5f * h2);
    float ix_max = fminf(cx1 + 0.5f * w1, cx2 + 0.5f * w2);
    float iy_max = fminf(cy1 + 0.5f * h1, cy2 + 0.5f * h2);
    float iw = fmaxf(ix_max - ix_min, 0.0f);
    float ih = fmaxf(iy_max - iy_min, 0.0f);
    float inter = iw * ih;
    float uni = w1 * h1 + w2 * h2 - inter;
    return inter / (uni + 1e-6f);
}

__global__ void __launch_bounds__(256)
yolo_loss_kernel(const float* __restrict__ pred,
                 const float* __restrict__ tgt,
                 float* __restrict__ out,
                 int ncells) {
    const unsigned FULL = 0xffffffffu;
    const int lane   = threadIdx.x & 31;
    const int wid    = threadIdx.x >> 5;
    const int gwarp  = blockIdx.x * 8 + wid;
    const int nwarps = gridDim.x * 8;
    const int nchunks = (ncells + 31) >> 5;

    __shared__ float s_w[8][32];
    __shared__ float s_red[8][4];

    float a_n = 0.0f, a_co = 0.0f, a_cf = 0.0f, a_cl = 0.0f;

    for (int chunk = gwarp; chunk < nchunks; chunk += nwarps) {
        const int base = chunk << 5;
        const int cell = base + lane;
        const bool valid = cell < ncells;

        // ---------- Phase 0: obj-flag gather -> per-warp weight LUT ----------
        float tcv0 = valid ? __ldg(tgt + (size_t)cell * DPC + 4) : 0.0f;
        s_w[wid][lane] = (tcv0 == 1.0f) ? 1.0f : 0.0f;
        __syncwarp();

        // ---------- Phase A: vectorized class-MSE stream ----------
        if (base + 32 <= ncells) {
            // full chunk: 720 float4s, 16B-aligned
            const float4* p4 = reinterpret_cast<const float4*>(pred + (size_t)base * DPC);
            const float4* t4 = reinterpret_cast<const float4*>(tgt  + (size_t)base * DPC);
            const float* wl = s_w[wid];
            float acc = 0.0f;

            #pragma unroll 2
            for (int it = 0; it < 22; ++it) {
                int idx = lane + (it << 5);
                float4 pv = p4[idx];
                float4 tv = t4[idx];
                unsigned f  = (unsigned)(idx << 2);
                unsigned c0 = f / 90u;
                int e0 = (int)(f - 90u * c0);
                float w = wl[c0];
                float w01 = (e0 >= 10) ? w : 0.0f;
                float w23 = (e0 >= 8 && e0 < 88) ? w : 0.0f;
                float d0 = pv.x - tv.x, d1 = pv.y - tv.y;
                float d2 = pv.z - tv.z, d3 = pv.w - tv.w;
                acc = fmaf(w01, fmaf(d0, d0, d1 * d1), acc);
                acc = fmaf(w23, fmaf(d2, d2, d3 * d3), acc);
            }
            if (lane < 16) {                      // tail: float4s 704..719
                int idx = lane + 704;
                float4 pv = p4[idx];
                float4 tv = t4[idx];
                unsigned f  = (unsigned)(idx << 2);
                unsigned c0 = f / 90u;
                int e0 = (int)(f - 90u * c0);
                float w = wl[c0];
                float w01 = (e0 >= 10) ? w : 0.0f;
                float w23 = (e0 >= 8 && e0 < 88) ? w : 0.0f;
                float d0 = pv.x - tv.x, d1 = pv.y - tv.y;
                float d2 = pv.z - tv.z, d3 = pv.w - tv.w;
                acc = fmaf(w01, fmaf(d0, d0, d1 * d1), acc);
                acc = fmaf(w23, fmaf(d2, d2, d3 * d3), acc);
            }
            a_cl += acc;
        } else {
            // partial chunk fallback (never taken for B*49 % 32 == 0 sizes)
            const int jmax = ncells - base;
            for (int j = 0; j < jmax; ++j) {
                float w = s_w[wid][j];
                if (w != 0.0f) {
                    const float* p = pred + (size_t)(base + j) * DPC;
                    const float* t = tgt  + (size_t)(base + j) * DPC;
                    float cs = 0.0f;
                    for (int k = 10 + lane; k < DPC; k += 32) {
                        float d = p[k] - t[k];
                        cs = fmaf(d, d, cs);
                    }
                    a_cl += cs;     // per-lane partial; reduced at the end
                }
            }
        }

        // ---------- Phase B: lane-per-cell box math (L1-resident lines) ----------
        if (valid) {
            const float2* pb = reinterpret_cast<const float2*>(pred + (size_t)cell * DPC);
            const float2* tb = reinterpret_cast<const float2*>(tgt  + (size_t)cell * DPC);
            float2 q0 = pb[0], q1 = pb[1], q2 = pb[2], q3 = pb[3], q4 = pb[4];
            float2 r0 = tb[0], r1 = tb[1], r2 = tb[2];

            float bx1 = q0.x, by1 = q0.y, bw1 = q1.x, bh1 = q1.y, bc1 = q2.x;
            float bx2 = q2.y, by2 = q3.x, bw2 = q3.y, bh2 = q4.x, bc2 = q4.y;
            float tx = r0.x, ty = r0.y, tw = r1.x, th = r1.y, tcv = r2.x;

            int gx = cell % GRID_S;
            int gy = (cell / GRID_S) % GRID_S;
            const float inv = 1.0f / (float)GRID_S;
            float fgx = (float)gx, fgy = (float)gy;

            float c1x = (fgx + bx1) * inv, c1y = (fgy + by1) * inv;
            float c2x = (fgx + bx2) * inv, c2y = (fgy + by2) * inv;
            float ctx = (fgx + tx)  * inv, cty = (fgy + ty)  * inv;

            float iou1 = iou_img(c1x, c1y, bw1, bh1, ctx, cty, tw, th);
            float iou2 = iou_img(c2x, c2y, bw2, bh2, ctx, cty, tw, th);
            bool r1sel = iou1 > iou2;

            float bx = r1sel ? bx1 : bx2;
            float by = r1sel ? by1 : by2;
            float bw = r1sel ? bw1 : bw2;
            float bh = r1sel ? bh1 : bh2;
            float bc = r1sel ? bc1 : bc2;

            float objf = (tcv == 1.0f) ? 1.0f : 0.0f;

            float dx = bx - tx, dy = by - ty;
            float dxy2 = dx * dx + dy * dy;
            float sw = sqrtf(fmaxf(bw, 1e-6f)) - sqrtf(fmaxf(tw, 1e-6f));
            float sh = sqrtf(fmaxf(bh, 1e-6f)) - sqrtf(fmaxf(th, 1e-6f));
            float coord_per = 0.5f * (dxy2 + sw * sw + sh * sh);

            float co = bc - 1.0f;
            float conf = (objf != 0.0f) ? (co * co)
                                        : 0.5f * (bc1 * bc1 + bc2 * bc2);

            a_n  += objf;
            a_co += coord_per * objf;
            a_cf += conf;
        }
    }

    // ---------- warp reduction ----------
    #pragma unroll
    for (int off = 16; off; off >>= 1) {
        a_n  += __shfl_down_sync(FULL, a_n,  off);
        a_co += __shfl_down_sync(FULL, a_co, off);
        a_cf += __shfl_down_sync(FULL, a_cf, off);
        a_cl += __shfl_down_sync(FULL, a_cl, off);
    }
    if (lane == 0) {
        s_red[wid][0] = a_n;
        s_red[wid][1] = a_co;
        s_red[wid][2] = a_cf;
        s_red[wid][3] = a_cl;
    }
    __syncthreads();

    // ---------- block -> global (REDG) ----------
    if (threadIdx.x < 4) {
        float s = 0.0f;
        #pragma unroll
        for (int w = 0; w < 8; ++w) s += s_red[w][threadIdx.x];
        atomicAdd(&g_acc[threadIdx.x], s);
    }
    __syncthreads();

    // ---------- last-block finalize (self-resetting) ----------
    if (threadIdx.x == 0) {
        __threadfence();
        unsigned int ticket = atomicAdd(&g_done, 1u);
        if (ticket == gridDim.x - 1) {
            __threadfence();
            volatile float* ga = g_acc;
            float n  = ga[0];
            float co = ga[1];
            float cf = ga[2];
            float cl = ga[3];
            float den = fmaxf(n, 1.0f);
            float conf_count = fmaxf(2.0f * (float)ncells - n, 1.0f);
            out[0] = 5.0f * (co / den) + cf / conf_count
                   + (cl * (1.0f / 80.0f)) / den;
            ga[0] = 0.0f; ga[1] = 0.0f; ga[2] = 0.0f; ga[3] = 0.0f;
            __threadfence();
            g_done = 0u;
        }
    }
}

extern "C" void kernel_launch(void* const* d_in, const int* in_sizes, int n_in,
                              void* d_out, int out_size) {
    const float* pred = (const float*)d_in[0];
    const float* tgt  = (const float*)d_in[1];
    float* out = (float*)d_out;

    int ncells  = in_sizes[0] / DPC;       // B * S * S
    int nchunks = (ncells + 31) / 32;
    int blocks  = (nchunks + 7) / 8;       // 8 warps/block, 1 chunk per warp

    yolo_loss_kernel<<<blocks, 256>>>(pred, tgt, out, ncells);
}

// round 6
// speedup vs baseline: 1.7452x; 1.0615x over previous
#include <cuda_runtime.h>

#define DPC 90            // 10 + 80 classes
#define GRID_S 7

// accumulators: [0]=n_obj, [1]=coord_sum, [2]=conf_sum, [3]=class_sum
__device__ float g_acc[4];
__device__ unsigned int g_done;

__device__ __forceinline__ float iou_img(float cx1, float cy1, float w1, float h1,
                                         float cx2, float cy2, float w2, float h2) {
    float ix_min = fmaxf(cx1 - 0.5f * w1, cx2 - 0.5f * w2);
    float iy_min = fmaxf(cy1 - 0.5f * h1, cy2 - 0.5f * h2);
    float ix_max = fminf(cx1 + 0.5f * w1, cx2 + 0.5f * w2);
    float iy_max = fminf(cy1 + 0.5f * h1, cy2 + 0.5f * h2);
    float iw = fmaxf(ix_max - ix_min, 0.0f);
    float ih = fmaxf(iy_max - iy_min, 0.0f);
    float inter = iw * ih;
    float uni = w1 * h1 + w2 * h2 - inter;
    return inter / (uni + 1e-6f);
}

__global__ void __launch_bounds__(128, 12)
yolo_loss_kernel(const float* __restrict__ pred,
                 const float* __restrict__ tgt,
                 float* __restrict__ out,
                 int ncells) {
    const unsigned FULL = 0xffffffffu;
    const int lane   = threadIdx.x & 31;
    const int wid    = threadIdx.x >> 5;          // 0..3
    const int gwarp  = blockIdx.x * 4 + wid;
    const int nwarps = gridDim.x * 4;
    const int nchunks = (ncells + 31) >> 5;

    __shared__ float s_red[4][4];

    float a_n = 0.0f, a_co = 0.0f, a_cf = 0.0f, a_cl = 0.0f;

    for (int chunk = gwarp; chunk < nchunks; chunk += nwarps) {
        const int base = chunk << 5;
        const int cell = base + lane;
        const bool valid = cell < ncells;

        // ---------- obj flag into register (no barrier, no smem) ----------
        float tcv0 = valid ? __ldg(tgt + (size_t)cell * DPC + 4) : 0.0f;
        float flag = (tcv0 == 1.0f) ? 1.0f : 0.0f;

        // ---------- Phase A: vectorized class-MSE stream ----------
        if (base + 32 <= ncells) {
            const float4* p4 = reinterpret_cast<const float4*>(pred + (size_t)base * DPC);
            const float4* t4 = reinterpret_cast<const float4*>(tgt  + (size_t)base * DPC);
            float acc = 0.0f;

            #pragma unroll 2
            for (int it = 0; it < 22; ++it) {
                int idx = lane + (it << 5);
                float4 pv = p4[idx];
                float4 tv = t4[idx];
                unsigned f  = (unsigned)(idx << 2);
                unsigned c0 = f / 90u;
                int e0 = (int)(f - 90u * c0);
                float w = __shfl_sync(FULL, flag, (int)c0);
                float w01 = (e0 >= 10) ? w : 0.0f;
                float w23 = (e0 >= 8 && e0 < 88) ? w : 0.0f;
                float d0 = pv.x - tv.x, d1 = pv.y - tv.y;
                float d2 = pv.z - tv.z, d3 = pv.w - tv.w;
                acc = fmaf(w01, fmaf(d0, d0, d1 * d1), acc);
                acc = fmaf(w23, fmaf(d2, d2, d3 * d3), acc);
            }
            {   // tail: float4s 704..719 (lanes 0..15)
                int idx = lane + 704;
                unsigned f  = (unsigned)(idx << 2);
                unsigned c0 = f / 90u;
                int e0 = (int)(f - 90u * c0);
                float w = __shfl_sync(FULL, flag, (int)(c0 & 31u));
                if (lane < 16) {
                    float4 pv = p4[idx];
                    float4 tv = t4[idx];
                    float w01 = (e0 >= 10) ? w : 0.0f;
                    float w23 = (e0 >= 8 && e0 < 88) ? w : 0.0f;
                    float d0 = pv.x - tv.x, d1 = pv.y - tv.y;
                    float d2 = pv.z - tv.z, d3 = pv.w - tv.w;
                    acc = fmaf(w01, fmaf(d0, d0, d1 * d1), acc);
                    acc = fmaf(w23, fmaf(d2, d2, d3 * d3), acc);
                }
            }
            a_cl += acc;
        } else {
            // partial chunk fallback (not taken when ncells % 32 == 0)
            const int jmax = ncells - base;
            for (int j = 0; j < jmax; ++j) {
                float w = __shfl_sync(FULL, flag, j);
                if (w != 0.0f) {
                    const float* p = pred + (size_t)(base + j) * DPC;
                    const float* t = tgt  + (size_t)(base + j) * DPC;
                    float cs = 0.0f;
                    for (int k = 10 + lane; k < DPC; k += 32) {
                        float d = p[k] - t[k];
                        cs = fmaf(d, d, cs);
                    }
                    a_cl += cs;
                }
            }
        }

        // ---------- Phase B: lane-per-cell box math (L2-resident lines) ----------
        if (valid) {
            const float2* pb = reinterpret_cast<const float2*>(pred + (size_t)cell * DPC);
            const float2* tb = reinterpret_cast<const float2*>(tgt  + (size_t)cell * DPC);
            float2 q0 = pb[0], q1 = pb[1], q2 = pb[2], q3 = pb[3], q4 = pb[4];
            float2 r0 = tb[0], r1 = tb[1];

            float bx1 = q0.x, by1 = q0.y, bw1 = q1.x, bh1 = q1.y, bc1 = q2.x;
            float bx2 = q2.y, by2 = q3.x, bw2 = q3.y, bh2 = q4.x, bc2 = q4.y;
            float tx = r0.x, ty = r0.y, tw = r1.x, th = r1.y;

            int gx = cell % GRID_S;
            int gy = (cell / GRID_S) % GRID_S;
            const float inv = 1.0f / (float)GRID_S;
            float fgx = (float)gx, fgy = (float)gy;

            float c1x = (fgx + bx1) * inv, c1y = (fgy + by1) * inv;
            float c2x = (fgx + bx2) * inv, c2y = (fgy + by2) * inv;
            float ctx = (fgx + tx)  * inv, cty = (fgy + ty)  * inv;

            float iou1 = iou_img(c1x, c1y, bw1, bh1, ctx, cty, tw, th);
            float iou2 = iou_img(c2x, c2y, bw2, bh2, ctx, cty, tw, th);
            bool r1sel = iou1 > iou2;

            float bx = r1sel ? bx1 : bx2;
            float by = r1sel ? by1 : by2;
            float bw = r1sel ? bw1 : bw2;
            float bh = r1sel ? bh1 : bh2;
            float bc = r1sel ? bc1 : bc2;

            float objf = flag;   // (tcv == 1.0f) already evaluated

            float dx = bx - tx, dy = by - ty;
            float dxy2 = dx * dx + dy * dy;
            float sw = sqrtf(fmaxf(bw, 1e-6f)) - sqrtf(fmaxf(tw, 1e-6f));
            float sh = sqrtf(fmaxf(bh, 1e-6f)) - sqrtf(fmaxf(th, 1e-6f));
            float coord_per = 0.5f * (dxy2 + sw * sw + sh * sh);

            float co = bc - 1.0f;
            float conf = (objf != 0.0f) ? (co * co)
                                        : 0.5f * (bc1 * bc1 + bc2 * bc2);

            a_n  += objf;
            a_co += coord_per * objf;
            a_cf += conf;
        }
    }

    // ---------- warp reduction ----------
    #pragma unroll
    for (int off = 16; off; off >>= 1) {
        a_n  += __shfl_down_sync(FULL, a_n,  off);
        a_co += __shfl_down_sync(FULL, a_co, off);
        a_cf += __shfl_down_sync(FULL, a_cf, off);
        a_cl += __shfl_down_sync(FULL, a_cl, off);
    }
    if (lane == 0) {
        s_red[wid][0] = a_n;
        s_red[wid][1] = a_co;
        s_red[wid][2] = a_cf;
        s_red[wid][3] = a_cl;
    }
    __syncthreads();

    // ---------- block -> global (REDG) ----------
    if (threadIdx.x < 4) {
        float s = 0.0f;
        #pragma unroll
        for (int w = 0; w < 4; ++w) s += s_red[w][threadIdx.x];
        atomicAdd(&g_acc[threadIdx.x], s);
    }
    __syncthreads();

    // ---------- last-block finalize (self-resetting) ----------
    if (threadIdx.x == 0) {
        __threadfence();
        unsigned int ticket = atomicAdd(&g_done, 1u);
        if (ticket == gridDim.x - 1) {
            __threadfence();
            volatile float* ga = g_acc;
            float n  = ga[0];
            float co = ga[1];
            float cf = ga[2];
            float cl = ga[3];
            float den = fmaxf(n, 1.0f);
            float conf_count = fmaxf(2.0f * (float)ncells - n, 1.0f);
            out[0] = 5.0f * (co / den) + cf / conf_count
                   + (cl * (1.0f / 80.0f)) / den;
            ga[0] = 0.0f; ga[1] = 0.0f; ga[2] = 0.0f; ga[3] = 0.0f;
            __threadfence();
            g_done = 0u;
        }
    }
}

extern "C" void kernel_launch(void* const* d_in, const int* in_sizes, int n_in,
                              void* d_out, int out_size) {
    const float* pred = (const float*)d_in[0];
    const float* tgt  = (const float*)d_in[1];
    float* out = (float*)d_out;

    int ncells  = in_sizes[0] / DPC;       // B * S * S
    int nchunks = (ncells + 31) / 32;      // one 32-cell chunk per warp
    int blocks  = (nchunks + 3) / 4;       // 4 warps per block (128 threads)

    yolo_loss_kernel<<<blocks, 128>>>(pred, tgt, out, ncells);
}